// round 5
// baseline (speedup 1.0000x reference)
#include <cuda_runtime.h>

// Sineconv: out[b,l,f] = sum_{w=0}^{64} x[b, l + 2f + ((f+w)>>5)] * sines[f, l+w]
//                        + x[b, l+32] * res_kernel[f]
// sines[f,s] = amplitude[f] * sin( ((frequency[f]*19000)*2pi) * sine_range[s] + phases[f]*2pi )
//
// x factor is piecewise-constant in w over 3 ranges -> each output needs only
// 3 contiguous range-sums of sines (fp32 prefix scan) + residual.
//
// R5: vectorized epilogue. x staged batch-packed as float4 (16 scalar LDS -> 4
// LDS.128 per pass); A-coefficients {A0,A1,A2,rk} precomputed per (f,i) in a
// conflict-free warp-local phase and read as one LDS.128 (was 4 conflicted
// scalar LDS + rk). Block = (l-tile 64, f-group 8), grid 1020.

#define S_TOTAL 16384
#define L_OUT   16320
#define F_N     32
#define B_N     4
#define TILE_L  64
#define FG      8               // features per block
#define NS      (TILE_L + 65)   // 129 sine samples per tile (with halo)
#define NPP     132             // Psh row stride
#define ASTRIDE 65              // Ash row stride in float4: (w*65+i)%8 = (w+i)%8 -> CF

// Accurate sinf via fp32 FMA Cody-Waite (exact internal products).
// |arg| <= ~1e5 here: total reduction error ~6e-8 rad.
__device__ __forceinline__ float acc_sinf(float a) {
    float kf = rintf(a * 0.63661977236758134f);          // 2/pi
    float r  = fmaf(-kf, 1.57079637050628662e+0f, a);    // c1 = float(pi/2)
    r        = fmaf(-kf, -4.37113900018624283e-8f, r);   // c2 = float(pi/2 - c1)
    int   q  = (int)kf;
    float r2 = r * r;
    float sp = fmaf(r2, fmaf(r2, fmaf(r2, -1.9841269841e-4f, 8.3333333333e-3f),
                             -1.6666666667e-1f), 1.0f);
    float s  = r * sp;
    float c  = fmaf(r2, fmaf(r2, fmaf(r2, fmaf(r2, 2.4801587302e-5f, -1.3888888889e-3f),
                             4.1666666667e-2f), -5.0e-1f), 1.0f);
    float v = (q & 1) ? c : s;
    return (q & 2) ? -v : v;
}

__global__ __launch_bounds__(256) void sineconv_kernel(
    const float* __restrict__ x,          // (B, S, 1)
    const float* __restrict__ sr,         // (S,)
    const float* __restrict__ phases,     // (32,)
    const float* __restrict__ amplitude,  // (32,)
    const float* __restrict__ frequency,  // (32,)
    const float* __restrict__ res_kernel, // (32,)
    float* __restrict__ out)              // (B, L, F)
{
    __shared__ float  Psh[FG][NPP];         // exclusive sine prefix per row (no amp)
    __shared__ float4 xsh4[NS + 2];         // batch-packed x: {b0,b1,b2,b3} per sample
    __shared__ float  srsh[NS];
    __shared__ float4 Ash[FG * ASTRIDE];    // {A0,A1,A2,rk} per (fl, i)

    const int tid  = threadIdx.x;
    const int lane = tid & 31;
    const int warp = tid >> 5;
    const int s0   = blockIdx.x * TILE_L;
    const int fg0  = blockIdx.y * FG;

    // ---- stage: x halo packed over batch, and sr tile ----
    if (tid < NS + 2) {                      // samples s0 .. s0+130
        int s = s0 + tid;
        float4 v;
        v.x = (s < S_TOTAL) ? x[0 * S_TOTAL + s] : 0.0f;
        v.y = (s < S_TOTAL) ? x[1 * S_TOTAL + s] : 0.0f;
        v.z = (s < S_TOTAL) ? x[2 * S_TOTAL + s] : 0.0f;
        v.w = (s < S_TOTAL) ? x[3 * S_TOTAL + s] : 0.0f;
        xsh4[tid] = v;
    }
    if (tid < NS) {
        int s = s0 + tid;
        srsh[tid] = (s < S_TOTAL) ? sr[s] : 0.0f;
    }
    __syncthreads();

    // ---- phase 1: sines + fp32 prefix scan; warp w owns feature row w ----
    {
        const float TWO_PI = 6.28318530717958647692f;
        const int f = fg0 + warp;
        // Replicate reference fp32 rounding: ((freq*19000)*2pi)*sr + ph
        float w2  = __fmul_rn(__fmul_rn(frequency[f], 19000.0f), TWO_PI);
        float ph  = __fmul_rn(phases[f], TWO_PI);

        // each lane owns exactly 4 consecutive samples: j = 4*lane + k (0..127)
        float loc[4];
        float run = 0.0f;
        int j0 = lane * 4;
#pragma unroll
        for (int k = 0; k < 4; k++) {
            int j = j0 + k;
            float v = 0.0f;
            if ((s0 + j) < S_TOTAL) {
                float arg = __fadd_rn(__fmul_rn(w2, srsh[j]), ph);
                v = acc_sinf(arg);
            }
            run += v;
            loc[k] = run;
        }
        // exclusive scan of lane totals across the warp
        float t = run;
#pragma unroll
        for (int off = 1; off < 32; off <<= 1) {
            float n = __shfl_up_sync(0xFFFFFFFFu, t, off);
            if (lane >= off) t += n;
        }
        float excl = t - run;
        if (lane == 0) Psh[warp][0] = 0.0f;
#pragma unroll
        for (int k = 0; k < 4; k++) {
            Psh[warp][1 + j0 + k] = excl + loc[k];
        }
        // final sample j = 128: appended by lane 31 only
        if (lane == 31) {
            float v = 0.0f;
            if ((s0 + 128) < S_TOTAL) {
                float arg = __fadd_rn(__fmul_rn(w2, srsh[128]), ph);
                v = acc_sinf(arg);
            }
            Psh[warp][1 + 128] = (excl + loc[3]) + v;
        }
        __syncwarp();

        // ---- phase 2 (warp-local, no block barrier): A coefficients ----
        // lanes along i: all Psh reads lane-consecutive -> conflict-free.
        float amp = amplitude[f];
        float rk  = res_kernel[f];
        int i32 = 32 - f;
        int i64 = 64 - f;
#pragma unroll
        for (int p = 0; p < 2; p++) {
            int i = lane + 32 * p;           // 0..63
            float p0 = Psh[warp][i];
            float pa = Psh[warp][i + i32];
            float pb = Psh[warp][i + i64];
            float p3 = Psh[warp][i + 65];
            float4 a;
            a.x = amp * (pa - p0);           // sum sines[f, l .. l+31-f]
            a.y = amp * (pb - pa);           // sum sines[f, l+32-f .. l+63-f]
            a.z = amp * (p3 - pb);           // sum sines[f, l+64-f .. l+64]
            a.w = rk;
            Ash[warp * ASTRIDE + i] = a;     // STS.128, (warp+i)%8 bank-groups: CF
        }
    }
    __syncthreads();

    // ---- phase 3: thread -> (fl = tid&7, i0 = tid>>3), 2 l-passes ----
    const int fl = tid & 7;
    const int f  = fg0 + fl;
    const int i0 = tid >> 3;                 // 0..31

#pragma unroll
    for (int p = 0; p < 2; p++) {
        int i = i0 + 32 * p;                 // local l index, 0..63
        int l = s0 + i;
        float4 a  = Ash[fl * ASTRIDE + i];   // LDS.128, conflict-free
        int xb = i + 2 * f;
        float4 x0 = xsh4[xb];
        float4 x1 = xsh4[xb + 1];
        float4 x2 = xsh4[xb + 2];
        float4 xr = xsh4[i + 32];
        int base = l * F_N + f;
        out[0 * L_OUT * F_N + base] = fmaf(x0.x, a.x, fmaf(x1.x, a.y, fmaf(x2.x, a.z, xr.x * a.w)));
        out[1 * L_OUT * F_N + base] = fmaf(x0.y, a.x, fmaf(x1.y, a.y, fmaf(x2.y, a.z, xr.y * a.w)));
        out[2 * L_OUT * F_N + base] = fmaf(x0.z, a.x, fmaf(x1.z, a.y, fmaf(x2.z, a.z, xr.z * a.w)));
        out[3 * L_OUT * F_N + base] = fmaf(x0.w, a.x, fmaf(x1.w, a.y, fmaf(x2.w, a.z, xr.w * a.w)));
    }
}

extern "C" void kernel_launch(void* const* d_in, const int* in_sizes, int n_in,
                              void* d_out, int out_size) {
    const float* x    = (const float*)d_in[0];
    const float* sr   = (const float*)d_in[1];
    const float* ph   = (const float*)d_in[2];
    const float* amp  = (const float*)d_in[3];
    const float* freq = (const float*)d_in[4];
    const float* rk   = (const float*)d_in[5];
    float* out = (float*)d_out;

    dim3 grid(L_OUT / TILE_L, F_N / FG);
    sineconv_kernel<<<grid, 256>>>(x, sr, ph, amp, freq, rk, out);
}

// round 6
// speedup vs baseline: 1.1791x; 1.1791x over previous
#include <cuda_runtime.h>

// Sineconv: out[b,l,f] = sum_{w=0}^{64} x[b, l + 2f + ((f+w)>>5)] * sines[f, l+w]
//                        + x[b, l+32] * res_kernel[f]
// sines[f,s] = amplitude[f] * sin( ((frequency[f]*19000)*2pi) * sine_range[s] + phases[f]*2pi )
//
// x factor is piecewise-constant in w over 3 ranges -> each output needs
// 3 contiguous range-sums of sines (local fp32 prefix scan) + residual.
//
// R6: two kernels. K1 fills a global sine table (each (f,s) computed ONCE,
// fully parallel, float4 I/O). K2 = R4 structure, but phase 1 loads its
// 128-sample window per row with one LDG.128/lane instead of recomputing
// sines (halo had caused 2.02x recompute on the critical path). One barrier.

#define S_TOTAL 16384
#define L_OUT   16320
#define F_N     32
#define B_N     4
#define TILE_L  64
#define FG      8               // features per block
#define NPP     132             // Psh row stride; entries 0..128 used
#define XW      (TILE_L + 68)   // padded x stage width

__device__ float g_sine[F_N * S_TOTAL];   // 2 MB sine table: amp[f]*sin(arg[f,s])

// Accurate sinf via fp32 FMA Cody-Waite (exact internal products).
// |arg| <= ~1e5 here: total reduction error ~6e-8 rad.
__device__ __forceinline__ float acc_sinf(float a) {
    float kf = rintf(a * 0.63661977236758134f);          // 2/pi
    float r  = fmaf(-kf, 1.57079637050628662e+0f, a);    // c1 = float(pi/2)
    r        = fmaf(-kf, -4.37113900018624283e-8f, r);   // c2 = float(pi/2 - c1)
    int   q  = (int)kf;
    float r2 = r * r;
    float sp = fmaf(r2, fmaf(r2, fmaf(r2, -1.9841269841e-4f, 8.3333333333e-3f),
                             -1.6666666667e-1f), 1.0f);
    float s  = r * sp;
    float c  = fmaf(r2, fmaf(r2, fmaf(r2, fmaf(r2, 2.4801587302e-5f, -1.3888888889e-3f),
                             4.1666666667e-2f), -5.0e-1f), 1.0f);
    float v = (q & 1) ? c : s;
    return (q & 2) ? -v : v;
}

// ---- kernel 1: sine table. grid (16, 32), 256 thr; 4 sines/thread (float4) ----
__global__ __launch_bounds__(256) void sine_table_kernel(
    const float* __restrict__ sr,
    const float* __restrict__ phases,
    const float* __restrict__ amplitude,
    const float* __restrict__ frequency)
{
    const float TWO_PI = 6.28318530717958647692f;
    const int f = blockIdx.y;
    const int s4 = (blockIdx.x * 256 + threadIdx.x);      // float4 index
    // Replicate reference fp32 rounding: ((freq*19000)*2pi)*sr + ph
    float w2  = __fmul_rn(__fmul_rn(frequency[f], 19000.0f), TWO_PI);
    float ph  = __fmul_rn(phases[f], TWO_PI);
    float amp = amplitude[f];

    float4 sv = ((const float4*)sr)[s4];
    float4 o;
    o.x = __fmul_rn(amp, acc_sinf(__fadd_rn(__fmul_rn(w2, sv.x), ph)));
    o.y = __fmul_rn(amp, acc_sinf(__fadd_rn(__fmul_rn(w2, sv.y), ph)));
    o.z = __fmul_rn(amp, acc_sinf(__fadd_rn(__fmul_rn(w2, sv.z), ph)));
    o.w = __fmul_rn(amp, acc_sinf(__fadd_rn(__fmul_rn(w2, sv.w), ph)));
    ((float4*)(g_sine + f * S_TOTAL))[s4] = o;
}

// ---- kernel 2: scan + epilogue. grid (255, 4), 256 thr ----
__global__ __launch_bounds__(256) void sineconv_kernel(
    const float* __restrict__ x,          // (B, S, 1)
    const float* __restrict__ res_kernel, // (32,)
    float* __restrict__ out)              // (B, L, F)
{
    __shared__ float Psh[FG][NPP];     // exclusive sine prefix per row
    __shared__ float xsh[B_N][XW];

    const int tid  = threadIdx.x;
    const int lane = tid & 31;
    const int warp = tid >> 5;
    const int s0   = blockIdx.x * TILE_L;
    const int fg0  = blockIdx.y * FG;

    // ---- stage x halo (s in [s0, s0+130]) ----
    for (int idx = tid; idx < B_N * (TILE_L + 67); idx += 256) {
        int b = idx / (TILE_L + 67);
        int i = idx - b * (TILE_L + 67);
        int s = s0 + i;
        xsh[b][i] = (s < S_TOTAL) ? x[b * S_TOTAL + s] : 0.0f;
    }

    // ---- phase 1: load 128-sample window + fp32 prefix scan; warp w owns row w ----
    {
        const int f = fg0 + warp;
        // lane's 4 consecutive samples via one LDG.128 (always in bounds:
        // s0 + 127 <= 16383 for all tiles)
        float4 v = ((const float4*)(g_sine + f * S_TOTAL + s0))[lane];
        float loc0 = v.x;
        float loc1 = loc0 + v.y;
        float loc2 = loc1 + v.z;
        float run  = loc2 + v.w;
        // exclusive scan of lane totals across the warp
        float t = run;
#pragma unroll
        for (int off = 1; off < 32; off <<= 1) {
            float n = __shfl_up_sync(0xFFFFFFFFu, t, off);
            if (lane >= off) t += n;
        }
        float excl = t - run;
        if (lane == 0) Psh[warp][0] = 0.0f;
        int j0 = lane * 4;
        Psh[warp][1 + j0]     = excl + loc0;
        Psh[warp][2 + j0]     = excl + loc1;
        Psh[warp][3 + j0]     = excl + loc2;
        Psh[warp][4 + j0]     = excl + run;   // entries 1..128; index 128 is max read
    }
    __syncthreads();

    // ---- epilogue: thread -> (fl = tid&7, i0 = tid>>3), 2 l-passes x 4 batches ----
    const int fl = tid & 7;
    const int f  = fg0 + fl;
    const int i0 = tid >> 3;             // 0..31
    const float rk = res_kernel[f];
    const int i32 = 32 - f;
    const int i64 = 64 - f;

#pragma unroll
    for (int p = 0; p < 2; p++) {
        int i = i0 + p * 32;             // local l index, 0..63
        int l = s0 + i;                  // grid exact: l < L_OUT always
        float p0 = Psh[fl][i];
        float pa = Psh[fl][i + i32];
        float pb = Psh[fl][i + i64];
        float p3 = Psh[fl][i + 65];
        float A0 = pa - p0;              // sum sines[f, l .. l+31-f]
        float A1 = pb - pa;              // sum sines[f, l+32-f .. l+63-f]
        float A2 = p3 - pb;              // sum sines[f, l+64-f .. l+64]
        int xb = i + 2 * f;
#pragma unroll
        for (int b = 0; b < B_N; b++) {
            float r = fmaf(xsh[b][xb],     A0,
                      fmaf(xsh[b][xb + 1], A1,
                      fmaf(xsh[b][xb + 2], A2,
                           xsh[b][i + 32] * rk)));
            out[(b * L_OUT + l) * F_N + f] = r;
        }
    }
}

extern "C" void kernel_launch(void* const* d_in, const int* in_sizes, int n_in,
                              void* d_out, int out_size) {
    const float* x    = (const float*)d_in[0];
    const float* sr   = (const float*)d_in[1];
    const float* ph   = (const float*)d_in[2];
    const float* amp  = (const float*)d_in[3];
    const float* freq = (const float*)d_in[4];
    const float* rk   = (const float*)d_in[5];
    float* out = (float*)d_out;

    dim3 g1(S_TOTAL / (256 * 4), F_N);
    sine_table_kernel<<<g1, 256>>>(sr, ph, amp, freq);

    dim3 g2(L_OUT / TILE_L, F_N / FG);
    sineconv_kernel<<<g2, 256>>>(x, rk, out);
}